// round 5
// baseline (speedup 1.0000x reference)
#include <cuda_runtime.h>

#define FULLMASK 0xffffffffu
#define MAX_PATCHES 32768

// Scratch: per-patch raw channel sums (mean*64), 32768 x 32 floats = 4MB.
__device__ float g_emb[MAX_PATCHES * 32];

// 16-lane tree reduction (xor within a 16-lane half; both halves independent).
__device__ __forceinline__ float redsum16(float v) {
    v += __shfl_xor_sync(FULLMASK, v, 8);
    v += __shfl_xor_sync(FULLMASK, v, 4);
    v += __shfl_xor_sync(FULLMASK, v, 2);
    v += __shfl_xor_sync(FULLMASK, v, 1);
    return v;
}
__device__ __forceinline__ float redmax16(float v) {
    v = fmaxf(v, __shfl_xor_sync(FULLMASK, v, 8));
    v = fmaxf(v, __shfl_xor_sync(FULLMASK, v, 4));
    v = fmaxf(v, __shfl_xor_sync(FULLMASK, v, 2));
    v = fmaxf(v, __shfl_xor_sync(FULLMASK, v, 1));
    return v;
}

// ============================================================================
// K1: pure streaming reduction. One warp per patch; 16 x LDG.128 with 4-lane
// contiguity groups (8 lines/LDG); epilogue = 2 shfls + 1 predicated STG per
// pass, so warps get back to loading almost immediately.
// ============================================================================
__global__ void __launch_bounds__(256) reduce_kernel(
    const float* __restrict__ patch, int n_patches)
{
    const int wid  = threadIdx.x >> 5;
    const int lane = threadIdx.x & 31;
    const int n = blockIdx.x * 8 + wid;
    if (n >= n_patches) return;

    const float4* p4 = reinterpret_cast<const float4*>(patch) + (size_t)n * 512;

    float4 v[16];
#pragma unroll
    for (int t = 0; t < 16; t++) {
        const int p = t >> 2, q = t & 3;
        const int idx = p * 128 + (lane >> 2) * 16 + (lane & 3) + 4 * q;
        v[t] = p4[idx];
    }

#pragma unroll
    for (int p = 0; p < 4; p++) {
        float a = 0.0f;
#pragma unroll
        for (int q = 0; q < 4; q++) {
            const float4 x = v[p * 4 + q];
            a += (x.x + x.y) + (x.z + x.w);
        }
        a += __shfl_xor_sync(FULLMASK, a, 1);
        a += __shfl_xor_sync(FULLMASK, a, 2);
        if ((lane & 3) == 0)
            g_emb[n * 32 + p * 8 + (lane >> 2)] = a;   // raw channel sum
    }
}

// ============================================================================
// K2: router math. 2 patches per warp (16 lanes each, lane e = lane&15).
// Block of 256 threads handles 16 patches; keys + embeddings staged in smem.
// ============================================================================
__global__ void __launch_bounds__(256) router_kernel(
    const float* __restrict__ keys,
    const float* __restrict__ p_temp,
    const float* __restrict__ p_beta,
    const float* __restrict__ p_thr,
    float* __restrict__ out,
    int n_patches)
{
    __shared__ float s_keys[16 * 33];   // stride-33 pad: conflict-free
    __shared__ float s_emb[16][33];     // 16 patches x 32 channels, padded

    const int tid  = threadIdx.x;
    const int wid  = tid >> 5;
    const int lane = tid & 31;

    // Stage keys
    for (int i = tid; i < 16 * 32; i += 256)
        s_keys[(i >> 5) * 33 + (i & 31)] = keys[i];

    // Stage 16 patches' embeddings (512 floats, 2 per thread, coalesced)
    const int base = blockIdx.x * 512;
    {
        const int i0 = tid * 2;
        const float2 e2 = *reinterpret_cast<const float2*>(&g_emb[base + i0]);
        s_emb[i0 >> 5][i0 & 31]       = e2.x;
        s_emb[i0 >> 5][(i0 & 31) + 1] = e2.y;
    }
    __syncthreads();

    const float logit_temp = __ldg(p_temp);
    const float mask_beta  = __ldg(p_beta);
    const float thr_base   = __ldg(p_thr);

    const int sub = lane >> 4;          // which of the warp's 2 patches
    const int e   = lane & 15;          // expert index
    const int pl  = wid * 2 + sub;      // patch index within block (0..15)
    const int n   = blockIdx.x * 16 + pl;

    // ---- L2 norm: each lane squares 2 channels of its patch, 16-lane tree ----
    const float x0 = s_emb[pl][e * 2];
    const float x1 = s_emb[pl][e * 2 + 1];
    const float sq = redsum16(x0 * x0 + x1 * x1);
    const float denom = fmaxf(sqrtf(sq), 64.0f * 1e-12f);

    // ---- Logits: broadcast LDS on s_emb row, spread LDS on keys ----
    float dot = 0.0f;
#pragma unroll
    for (int c = 0; c < 32; c++)
        dot = fmaf(s_emb[pl][c], s_keys[e * 33 + c], dot);

    const float sl = (dot / denom) / logit_temp + 1e-8f;

    // ---- Softmax over 16 ----
    const float m  = redmax16(sl);
    const float ex = __expf(sl - m);
    const float S  = redsum16(ex);
    const float w  = ex / S;

    // ---- Rank (descending, stable); width-16 shuffles stay in-half ----
    int rank = 0;
#pragma unroll
    for (int j = 0; j < 16; j++) {
        const float wj = __shfl_sync(FULLMASK, w, j, 16);
        rank += (wj > w) || (wj == w && j < e);
    }

    // ---- Order statistics & moments ----
    const float s0    = redsum16(rank == 0 ? w : 0.0f);
    const float rest  = redsum16((rank >= 1 && rank <= 4) ? w : 0.0f) * 0.25f;
    const float kth   = redsum16(rank == 3 ? w : 0.0f);
    const float meanw = redsum16(w) * (1.0f / 16.0f);
    const float d     = w - meanw;
    const float varw  = redsum16(d * d) * (1.0f / 15.0f);
    const float stdw  = sqrtf(varw);
    const float ent   = -redsum16(w * __logf(w + 1e-18f));

    // ---- Adaptive threshold ----
    const float maxc = 1.0f - s0;
    const float entc = 1.0f - ent * (1.0f / 2.7725887222397811f);  // 1/log(16)
    float gap = (s0 - rest) / (s0 + 1e-8f);
    gap = fminf(fmaxf(gap, 0.0f), 1.0f);
    const float af = 0.4f * maxc + 0.3f * entc + 0.3f * gap;
    float adaptive = thr_base * (0.5f + af);
    const float min_thr = fmaxf(0.05f, meanw - 0.5f * stdw);
    const float max_thr = fminf(0.7f, s0 - 0.1f * stdw);
    adaptive = fminf(fmaxf(adaptive, min_thr), max_thr);
    adaptive = fminf(adaptive, kth * 0.9f);

    // ---- Soft mask + renormalize ----
    const float xx  = (mask_beta + 1e-8f) * (w - adaptive);
    const float sm  = 1.0f / (1.0f + __expf(-xx));
    const float wf  = w * sm;
    const float swf = redsum16(wf);
    const float o   = wf / fmaxf(swf, 1e-8f);

    // Every lane writes a unique element; warp covers 128 contiguous bytes.
    if (n < n_patches)
        out[(size_t)n * 16 + e] = o;
}

extern "C" void kernel_launch(void* const* d_in, const int* in_sizes, int n_in,
                              void* d_out, int out_size) {
    const float* patch = (const float*)d_in[0];
    const float* keys  = (const float*)d_in[1];
    const float* temp  = (const float*)d_in[2];
    const float* beta  = (const float*)d_in[3];
    const float* thr   = (const float*)d_in[4];
    float* out = (float*)d_out;

    int n_patches = in_sizes[0] / (32 * 8 * 8);
    if (n_patches > MAX_PATCHES) n_patches = MAX_PATCHES;

    const int blocks1 = (n_patches + 7) / 8;     // 8 patches / block (1 per warp)
    reduce_kernel<<<blocks1, 256>>>(patch, n_patches);

    const int blocks2 = (n_patches + 15) / 16;   // 16 patches / block (2 per warp)
    router_kernel<<<blocks2, 256>>>(keys, temp, beta, thr, out, n_patches);
}

// round 6
// speedup vs baseline: 1.0476x; 1.0476x over previous
#include <cuda_runtime.h>

#define FULLMASK 0xffffffffu

__device__ __forceinline__ float redsum16(float v) {
    v += __shfl_xor_sync(FULLMASK, v, 8);
    v += __shfl_xor_sync(FULLMASK, v, 4);
    v += __shfl_xor_sync(FULLMASK, v, 2);
    v += __shfl_xor_sync(FULLMASK, v, 1);
    return v;
}
__device__ __forceinline__ float redmax16(float v) {
    v = fmaxf(v, __shfl_xor_sync(FULLMASK, v, 8));
    v = fmaxf(v, __shfl_xor_sync(FULLMASK, v, 4));
    v = fmaxf(v, __shfl_xor_sync(FULLMASK, v, 2));
    v = fmaxf(v, __shfl_xor_sync(FULLMASK, v, 1));
    return v;
}

// Monolithic, software-pipelined: each warp handles 2 patches. Patch B's 16
// LDG.128 are issued BEFORE patch A's long shuffle epilogue, so the epilogue
// latency (~1500+ cyc of dependent SHFL/MUFU) hides B's DRAM latency instead
// of leaving the memory system idle.
__global__ void __launch_bounds__(256, 2) router_kernel(
    const float* __restrict__ patch,
    const float* __restrict__ keys,
    const float* __restrict__ p_temp,
    const float* __restrict__ p_beta,
    const float* __restrict__ p_thr,
    float* __restrict__ out,
    int n_patches)
{
    __shared__ float s_keys[16 * 33];   // stride-33 pad: conflict-free
    __shared__ float s_raw[8][32];      // per-warp channel sums (reused A then B)

    const int tid  = threadIdx.x;
    const int wid  = tid >> 5;
    const int lane = tid & 31;

    for (int i = tid; i < 16 * 32; i += 256)
        s_keys[(i >> 5) * 33 + (i & 31)] = keys[i];
    __syncthreads();

    const int n0 = blockIdx.x * 16 + wid * 2;   // this warp's first patch
    if (n0 >= n_patches) return;                 // warp-uniform exit

    const float logit_temp = __ldg(p_temp);
    const float mask_beta  = __ldg(p_beta);
    const float thr_base   = __ldg(p_thr);

    const int e = lane & 15;

    // Load-index: lane groups of 4 cover 64B contiguous chunks (8 lines/LDG).
    const int lidx0 = (lane >> 2) * 16 + (lane & 3);

    // ---- Prefetch patch A ----
    const float4* pA = reinterpret_cast<const float4*>(patch) + (size_t)n0 * 512;
    float4 v[16];
#pragma unroll
    for (int t = 0; t < 16; t++) {
        const int p = t >> 2, q = t & 3;
        v[t] = pA[p * 128 + lidx0 + 4 * q];
    }

    const bool haveB = (n0 + 1) < n_patches;

#pragma unroll
    for (int it = 0; it < 2; it++) {
        const int n = n0 + it;

        // ---- Reduce current patch's v -> channel sums in smem ----
#pragma unroll
        for (int p = 0; p < 4; p++) {
            float a = 0.0f;
#pragma unroll
            for (int q = 0; q < 4; q++) {
                const float4 x = v[p * 4 + q];
                a += (x.x + x.y) + (x.z + x.w);
            }
            a += __shfl_xor_sync(FULLMASK, a, 1);
            a += __shfl_xor_sync(FULLMASK, a, 2);
            if ((lane & 3) == 0)
                s_raw[wid][p * 8 + (lane >> 2)] = a;
        }
        __syncwarp();

        // ---- Issue next patch's loads BEFORE the epilogue (latency hiding) ----
        if (it == 0 && haveB) {
            const float4* pB = reinterpret_cast<const float4*>(patch) + (size_t)(n0 + 1) * 512;
#pragma unroll
            for (int t = 0; t < 16; t++) {
                const int p = t >> 2, q = t & 3;
                v[t] = pB[p * 128 + lidx0 + 4 * q];
            }
        }

        // ================= Epilogue for patch n (independent of v) =================
        const float rc = s_raw[wid][lane];
        float sq = rc * rc;
        sq += __shfl_xor_sync(FULLMASK, sq, 16);
        sq += __shfl_xor_sync(FULLMASK, sq, 8);
        sq += __shfl_xor_sync(FULLMASK, sq, 4);
        sq += __shfl_xor_sync(FULLMASK, sq, 2);
        sq += __shfl_xor_sync(FULLMASK, sq, 1);
        const float denom = fmaxf(sqrtf(sq), 64.0f * 1e-12f);

        float dot = 0.0f;
#pragma unroll
        for (int c = 0; c < 32; c++)
            dot = fmaf(s_raw[wid][c], s_keys[e * 33 + c], dot);

        const float sl = (dot / denom) / logit_temp + 1e-8f;

        const float m  = redmax16(sl);
        const float ex = __expf(sl - m);
        const float S  = redsum16(ex);
        const float w  = ex / S;

        int rank = 0;
#pragma unroll
        for (int j = 0; j < 16; j++) {
            const float wj = __shfl_sync(FULLMASK, w, j, 16);
            rank += (wj > w) || (wj == w && j < e);
        }

        const float s0    = redsum16(rank == 0 ? w : 0.0f);
        const float rest  = redsum16((rank >= 1 && rank <= 4) ? w : 0.0f) * 0.25f;
        const float kth   = redsum16(rank == 3 ? w : 0.0f);
        const float meanw = redsum16(w) * (1.0f / 16.0f);
        const float d     = w - meanw;
        const float varw  = redsum16(d * d) * (1.0f / 15.0f);
        const float stdw  = sqrtf(varw);
        const float ent   = -redsum16(w * __logf(w + 1e-18f));

        const float maxc = 1.0f - s0;
        const float entc = 1.0f - ent * (1.0f / 2.7725887222397811f);   // 1/log(16)
        float gap = (s0 - rest) / (s0 + 1e-8f);
        gap = fminf(fmaxf(gap, 0.0f), 1.0f);
        const float af = 0.4f * maxc + 0.3f * entc + 0.3f * gap;
        float adaptive = thr_base * (0.5f + af);
        const float min_thr = fmaxf(0.05f, meanw - 0.5f * stdw);
        const float max_thr = fminf(0.7f, s0 - 0.1f * stdw);
        adaptive = fminf(fmaxf(adaptive, min_thr), max_thr);
        adaptive = fminf(adaptive, kth * 0.9f);

        const float xx  = (mask_beta + 1e-8f) * (w - adaptive);
        const float sm  = 1.0f / (1.0f + __expf(-xx));
        const float wf  = w * sm;
        const float swf = redsum16(wf);
        const float o   = wf / fmaxf(swf, 1e-8f);

        if (lane < 16)
            out[(size_t)n * 16 + e] = o;
        // ===========================================================================

        if (it == 0) {
            if (!haveB) return;
            __syncwarp();   // s_raw reads done before next reduce overwrites
        }
    }
}

extern "C" void kernel_launch(void* const* d_in, const int* in_sizes, int n_in,
                              void* d_out, int out_size) {
    const float* patch = (const float*)d_in[0];
    const float* keys  = (const float*)d_in[1];
    const float* temp  = (const float*)d_in[2];
    const float* beta  = (const float*)d_in[3];
    const float* thr   = (const float*)d_in[4];
    float* out = (float*)d_out;

    const int n_patches = in_sizes[0] / (32 * 8 * 8);
    const int blocks = (n_patches + 15) / 16;   // 8 warps/block, 2 patches/warp
    router_kernel<<<blocks, 256>>>(patch, keys, temp, beta, thr, out, n_patches);
}

// round 7
// speedup vs baseline: 1.1020x; 1.0519x over previous
#include <cuda_runtime.h>

#define FULLMASK 0xffffffffu

__device__ __forceinline__ float redsum16(float v) {
    v += __shfl_xor_sync(FULLMASK, v, 8);
    v += __shfl_xor_sync(FULLMASK, v, 4);
    v += __shfl_xor_sync(FULLMASK, v, 2);
    v += __shfl_xor_sync(FULLMASK, v, 1);
    return v;
}
__device__ __forceinline__ float redmax16(float v) {
    v = fmaxf(v, __shfl_xor_sync(FULLMASK, v, 8));
    v = fmaxf(v, __shfl_xor_sync(FULLMASK, v, 4));
    v = fmaxf(v, __shfl_xor_sync(FULLMASK, v, 2));
    v = fmaxf(v, __shfl_xor_sync(FULLMASK, v, 1));
    return v;
}

// One warp per patch. Loads are FULLY coalesced: lane l reads float4 t*32+l,
// so each LDG.128 covers 512 contiguous aligned bytes = 4 lines = 4 L1tex
// wavefronts (vs 8 for the previous grouped pattern). Channel boundaries align
// with 16-lane halves: LDG t covers channels 2t (lanes 0-15) and 2t+1 (16-31).
// Batches of 4 LDGs keep v[] at 16 regs; launch_bounds(256,6) pins regs ~42
// for ~48 warps/SM (high-occupancy regime that R1 showed is required).
__global__ void __launch_bounds__(256, 6) router_kernel(
    const float* __restrict__ patch,
    const float* __restrict__ keys,
    const float* __restrict__ p_temp,
    const float* __restrict__ p_beta,
    const float* __restrict__ p_thr,
    float* __restrict__ out,
    int n_patches)
{
    __shared__ float s_keys[16 * 33];   // stride-33 pad: conflict-free
    __shared__ float s_raw[8][32];      // per-warp channel sums

    const int tid  = threadIdx.x;
    const int wid  = tid >> 5;
    const int lane = tid & 31;

    for (int i = tid; i < 16 * 32; i += 256)
        s_keys[(i >> 5) * 33 + (i & 31)] = keys[i];
    __syncthreads();

    const int n = blockIdx.x * 8 + wid;
    if (n >= n_patches) return;          // warp-uniform exit; no block syncs below

    const float logit_temp = __ldg(p_temp);
    const float mask_beta  = __ldg(p_beta);
    const float thr_base   = __ldg(p_thr);

    const float4* p4 = reinterpret_cast<const float4*>(patch) + (size_t)n * 512;

    // ---- Coalesced streaming reduce: 4 batches x 4 LDG.128 ----
#pragma unroll
    for (int b = 0; b < 4; b++) {
        float4 v[4];
#pragma unroll
        for (int k = 0; k < 4; k++)
            v[k] = p4[(b * 4 + k) * 32 + lane];
#pragma unroll
        for (int k = 0; k < 4; k++) {
            const int t = b * 4 + k;
            float s = (v[k].x + v[k].y) + (v[k].z + v[k].w);
            // width-16 xor tree (masks < 16 keep lanes within their half)
            s += __shfl_xor_sync(FULLMASK, s, 1);
            s += __shfl_xor_sync(FULLMASK, s, 2);
            s += __shfl_xor_sync(FULLMASK, s, 4);
            s += __shfl_xor_sync(FULLMASK, s, 8);
            if ((lane & 15) == 0)
                s_raw[wid][t * 2 + (lane >> 4)] = s;   // raw channel sum (mean*64)
        }
    }
    __syncwarp();

    // ---- L2 norm of raw channel sums ----
    const float rc = s_raw[wid][lane];
    float sq = rc * rc;
    sq += __shfl_xor_sync(FULLMASK, sq, 16);
    sq += __shfl_xor_sync(FULLMASK, sq, 8);
    sq += __shfl_xor_sync(FULLMASK, sq, 4);
    sq += __shfl_xor_sync(FULLMASK, sq, 2);
    sq += __shfl_xor_sync(FULLMASK, sq, 1);
    const float denom = fmaxf(sqrtf(sq), 64.0f * 1e-12f);

    // ---- Logits: lane e = lane&15 computes expert e (halves mirror) ----
    const int e = lane & 15;
    float dot = 0.0f;
#pragma unroll
    for (int c = 0; c < 32; c++)
        dot = fmaf(s_raw[wid][c], s_keys[e * 33 + c], dot);

    const float sl = (dot / denom) / logit_temp + 1e-8f;

    // ---- Softmax over 16 ----
    const float m  = redmax16(sl);
    const float ex = __expf(sl - m);
    const float S  = redsum16(ex);
    const float w  = ex / S;

    // ---- Rank (descending, stable) ----
    int rank = 0;
#pragma unroll
    for (int j = 0; j < 16; j++) {
        const float wj = __shfl_sync(FULLMASK, w, j, 16);
        rank += (wj > w) || (wj == w && j < e);
    }

    // ---- Order statistics & moments ----
    const float s0    = redsum16(rank == 0 ? w : 0.0f);
    const float rest  = redsum16((rank >= 1 && rank <= 4) ? w : 0.0f) * 0.25f;
    const float kth   = redsum16(rank == 3 ? w : 0.0f);
    const float meanw = redsum16(w) * (1.0f / 16.0f);
    const float d     = w - meanw;
    const float varw  = redsum16(d * d) * (1.0f / 15.0f);
    const float stdw  = sqrtf(varw);
    const float ent   = -redsum16(w * __logf(w + 1e-18f));

    // ---- Adaptive threshold ----
    const float maxc = 1.0f - s0;
    const float entc = 1.0f - ent * (1.0f / 2.7725887222397811f);   // 1/log(16)
    float gap = (s0 - rest) / (s0 + 1e-8f);
    gap = fminf(fmaxf(gap, 0.0f), 1.0f);
    const float af = 0.4f * maxc + 0.3f * entc + 0.3f * gap;
    float adaptive = thr_base * (0.5f + af);
    const float min_thr = fmaxf(0.05f, meanw - 0.5f * stdw);
    const float max_thr = fminf(0.7f, s0 - 0.1f * stdw);
    adaptive = fminf(fmaxf(adaptive, min_thr), max_thr);
    adaptive = fminf(adaptive, kth * 0.9f);

    // ---- Soft mask + renormalize ----
    const float x    = (mask_beta + 1e-8f) * (w - adaptive);
    const float sm   = 1.0f / (1.0f + __expf(-x));
    const float wf   = w * sm;
    const float swf  = redsum16(wf);
    const float o    = wf / fmaxf(swf, 1e-8f);

    if (lane < 16)
        out[(size_t)n * 16 + e] = o;
}

extern "C" void kernel_launch(void* const* d_in, const int* in_sizes, int n_in,
                              void* d_out, int out_size) {
    const float* patch = (const float*)d_in[0];
    const float* keys  = (const float*)d_in[1];
    const float* temp  = (const float*)d_in[2];
    const float* beta  = (const float*)d_in[3];
    const float* thr   = (const float*)d_in[4];
    float* out = (float*)d_out;

    const int n_patches = in_sizes[0] / (32 * 8 * 8);
    const int blocks = (n_patches + 7) / 8;   // 8 warps (patches) per block
    router_kernel<<<blocks, 256>>>(patch, keys, temp, beta, thr, out, n_patches);
}